// round 6
// baseline (speedup 1.0000x reference)
#include <cuda_runtime.h>
#include <cstdint>

#define NSEG 100000
#define NROWS_MAX 4000000
#define DIM 32
#define TPB 256
#define SCAN_BLOCKS ((NSEG + 255) / 256)   // 391

// Scratch (allocation-free rule => __device__ globals)
__device__ int g_counts[NSEG];
__device__ int g_offsets[NSEG];
__device__ int g_cursor[NSEG];
__device__ int g_block_sums[512];
__device__ int g_perm[NROWS_MAX];

// ---- Pass 1: histogram of segment counts (int atomics only) ----
__global__ void hist_kernel(const int4* __restrict__ idx4, int n4,
                            const int* __restrict__ idx, int nrows) {
    int i = blockIdx.x * blockDim.x + threadIdx.x;
    if (i < n4) {
        int4 v = idx4[i];
        if ((unsigned)v.x < NSEG) atomicAdd(&g_counts[v.x], 1);
        if ((unsigned)v.y < NSEG) atomicAdd(&g_counts[v.y], 1);
        if ((unsigned)v.z < NSEG) atomicAdd(&g_counts[v.z], 1);
        if ((unsigned)v.w < NSEG) atomicAdd(&g_counts[v.w], 1);
    }
    if (i == 0) {
        for (int r = n4 * 4; r < nrows; r++) {
            int s = idx[r];
            if ((unsigned)s < NSEG) atomicAdd(&g_counts[s], 1);
        }
    }
}

// ---- Pass 2a: per-256-chunk exclusive scan; chunk totals to g_block_sums ----
__global__ void scan_blocks_kernel() {
    __shared__ int s[256];
    int gid = blockIdx.x * 256 + threadIdx.x;
    int v = (gid < NSEG) ? g_counts[gid] : 0;
    s[threadIdx.x] = v;
    __syncthreads();
    for (int d = 1; d < 256; d <<= 1) {
        int t = (threadIdx.x >= d) ? s[threadIdx.x - d] : 0;
        __syncthreads();
        s[threadIdx.x] += t;
        __syncthreads();
    }
    if (gid < NSEG) g_offsets[gid] = s[threadIdx.x] - v;   // exclusive within chunk
    if (threadIdx.x == 255) g_block_sums[blockIdx.x] = s[255];
}

// ---- Pass 2b: exclusive scan of the chunk totals (single block) ----
__global__ void scan_tops_kernel(int nblk) {
    __shared__ int s[512];
    int v = (threadIdx.x < nblk) ? g_block_sums[threadIdx.x] : 0;
    s[threadIdx.x] = v;
    __syncthreads();
    for (int d = 1; d < 512; d <<= 1) {
        int t = (threadIdx.x >= d) ? s[threadIdx.x - d] : 0;
        __syncthreads();
        s[threadIdx.x] += t;
        __syncthreads();
    }
    if (threadIdx.x < nblk) g_block_sums[threadIdx.x] = s[threadIdx.x] - v;
}

// ---- Pass 2c: add chunk bases; init cursors ----
__global__ void add_back_kernel() {
    int i = blockIdx.x * blockDim.x + threadIdx.x;
    if (i < NSEG) {
        int off = g_offsets[i] + g_block_sums[i >> 8];
        g_offsets[i] = off;
        g_cursor[i] = off;
    }
}

// ---- Pass 3: scatter row ids into segment-sorted order ----
__global__ void scatter_ids_kernel(const int4* __restrict__ idx4, int n4,
                                   const int* __restrict__ idx, int nrows) {
    int i = blockIdx.x * blockDim.x + threadIdx.x;
    if (i < n4) {
        int4 v = idx4[i];
        int r = i * 4;
        if ((unsigned)v.x < NSEG) g_perm[atomicAdd(&g_cursor[v.x], 1)] = r;
        if ((unsigned)v.y < NSEG) g_perm[atomicAdd(&g_cursor[v.y], 1)] = r + 1;
        if ((unsigned)v.z < NSEG) g_perm[atomicAdd(&g_cursor[v.z], 1)] = r + 2;
        if ((unsigned)v.w < NSEG) g_perm[atomicAdd(&g_cursor[v.w], 1)] = r + 3;
    }
    if (i == 0) {
        for (int r = n4 * 4; r < nrows; r++) {
            int s = idx[r];
            if ((unsigned)s < NSEG) g_perm[atomicAdd(&g_cursor[s], 1)] = r;
        }
    }
}

// ---- Pass 4: gather-reduce. One warp per segment, lane = column. ----
// Each row read is one coalesced 128B warp load. Divide fused; no atomics.
__global__ void __launch_bounds__(TPB) gather_kernel(
    const float* __restrict__ x, float* __restrict__ out) {
    int warp = (blockIdx.x * blockDim.x + threadIdx.x) >> 5;
    int lane = threadIdx.x & 31;
    if (warp >= NSEG) return;

    int start = g_offsets[warp];
    int count = g_counts[warp];

    float acc = 0.0f;
    for (int base = 0; base < count; base += 32) {
        int n = count - base; if (n > 32) n = 32;
        int rid = (base + lane < count) ? g_perm[start + base + lane] : 0;
        for (int j = 0; j < n; j++) {
            int row = __shfl_sync(0xffffffffu, rid, j);
            acc += x[(long long)row * DIM + lane];
        }
    }
    float r = __frcp_rn(fmaxf((float)count, 1.0f));
    out[(long long)warp * DIM + lane] = acc * r;
}

extern "C" void kernel_launch(void* const* d_in, const int* in_sizes, int n_in,
                              void* d_out, int out_size) {
    const float* x = (const float*)d_in[0];
    const int* idx = (const int*)d_in[1];
    float* out = (float*)d_out;

    int nrows = in_sizes[1];
    int n4 = nrows >> 2;

    void* counts_ptr = nullptr;
    cudaGetSymbolAddress(&counts_ptr, g_counts);
    cudaMemsetAsync(counts_ptr, 0, (size_t)NSEG * sizeof(int), 0);

    int hb = (n4 + TPB - 1) / TPB;
    hist_kernel<<<hb, TPB>>>((const int4*)idx, n4, idx, nrows);

    scan_blocks_kernel<<<SCAN_BLOCKS, 256>>>();
    scan_tops_kernel<<<1, 512>>>(SCAN_BLOCKS);
    add_back_kernel<<<SCAN_BLOCKS, 256>>>();

    scatter_ids_kernel<<<hb, TPB>>>((const int4*)idx, n4, idx, nrows);

    int gwarps = NSEG;
    int gb = (gwarps * 32 + TPB - 1) / TPB;
    gather_kernel<<<gb, TPB>>>(x, out);
}

// round 7
// speedup vs baseline: 1.4584x; 1.4584x over previous
#include <cuda_runtime.h>
#include <cstdint>

#define NUM_SEG 100000
#define DIM 32
#define TPB 256
#define ROWS_PER_BLK 256
#define TILE_BYTES (ROWS_PER_BLK * DIM * 4)   // 32 KB

// Scratch: per-segment counts (allocation-free rule => __device__ global)
__device__ float g_counts[NUM_SEG];

__device__ __forceinline__ uint32_t smem_u32(const void* p) {
    uint32_t a;
    asm("{ .reg .u64 t; cvta.to.shared.u64 t, %1; cvt.u32.u64 %0, t; }" : "=r"(a) : "l"(p));
    return a;
}

// All-TMA scatter: one cp.async.bulk (32 KB) stages 256 rows in smem with zero
// LSU/register involvement; each thread then issues one cp.reduce.async.bulk
// (128 B f32-add) for its row. SM-side work is ~nothing; the pipeline is
// TMA-engine + L2-atomic-ALU, overlapped with the DRAM read stream.
__global__ void __launch_bounds__(TPB) scatter_kernel(
    const float* __restrict__ x,
    const int* __restrict__ index,
    float* __restrict__ out,
    int nrows)
{
    __shared__ __align__(128) float tile[ROWS_PER_BLK * DIM];  // 32 KB
    __shared__ __align__(8) unsigned long long mbar;

    int t = threadIdx.x;
    int row0 = blockIdx.x * ROWS_PER_BLK;
    bool full_tile = (row0 + ROWS_PER_BLK) <= nrows;

    if (full_tile) {
        if (t == 0) {
            uint32_t mb = smem_u32(&mbar);
            asm volatile("mbarrier.init.shared.b64 [%0], 1;" :: "r"(mb) : "memory");
        }
        __syncthreads();
        if (t == 0) {
            uint32_t mb = smem_u32(&mbar);
            uint32_t dst = smem_u32(tile);
            const float* src = x + (long long)row0 * DIM;
            asm volatile("mbarrier.arrive.expect_tx.shared.b64 _, [%0], %1;"
                         :: "r"(mb), "r"(TILE_BYTES) : "memory");
            asm volatile(
                "cp.async.bulk.shared::cta.global.mbarrier::complete_tx::bytes "
                "[%0], [%1], %2, [%3];"
                :: "r"(dst), "l"(src), "r"(TILE_BYTES), "r"(mb) : "memory");
        }
        // Wait for the bulk load (parity 0).
        {
            uint32_t mb = smem_u32(&mbar);
            asm volatile(
                "{\n\t.reg .pred P;\n"
                "WAIT_%=:\n\t"
                "mbarrier.try_wait.parity.shared.b64 P, [%0], 0, 0x989680;\n\t"
                "@!P bra WAIT_%=;\n\t}"
                :: "r"(mb) : "memory");
        }
    } else {
        // Tail tile: per-thread loads.
        for (int k = 0; k < 8; k++) {
            int local = t + k * TPB;                 // float4 chunk id
            int r = row0 + (local >> 3);
            if (r < nrows)
                ((float4*)tile)[local] = ((const float4*)x)[(long long)r * 8 + (local & 7)];
        }
        __syncthreads();
        asm volatile("fence.proxy.async.shared::cta;" ::: "memory");
    }

    int row = row0 + t;
    if (row < nrows) {
        int seg = index[row];
        if ((unsigned)seg < NUM_SEG) {
            uint32_t saddr = smem_u32(&tile[t * DIM]);
            float* gdst = out + (long long)seg * DIM;
            asm volatile(
                "cp.reduce.async.bulk.global.shared::cta.bulk_group.add.f32 [%0], [%1], %2;"
                :: "l"(gdst), "r"(saddr), "r"(DIM * 4) : "memory");
            atomicAdd(&g_counts[seg], 1.0f);
        }
    }
    // Drain this thread's bulk ops before CTA exit (smem read asynchronously).
    asm volatile("cp.async.bulk.commit_group;" ::: "memory");
    asm volatile("cp.async.bulk.wait_group 0;" ::: "memory");
}

// Grid-stride vectorized divide.
__global__ void __launch_bounds__(TPB) divide_kernel(float4* __restrict__ out4, int total4) {
    int stride = gridDim.x * blockDim.x;
    for (int i = blockIdx.x * blockDim.x + threadIdx.x; i < total4; i += stride) {
        float c = __ldg(&g_counts[i >> 3]);          // 8 float4 per row of 32
        float r = __frcp_rn(fmaxf(c, 1.0f));
        float4 v = out4[i];
        v.x *= r; v.y *= r; v.z *= r; v.w *= r;
        out4[i] = v;
    }
}

extern "C" void kernel_launch(void* const* d_in, const int* in_sizes, int n_in,
                              void* d_out, int out_size) {
    const float* x = (const float*)d_in[0];
    const int* index = (const int*)d_in[1];
    float* out = (float*)d_out;

    int nrows = in_sizes[1];   // 4,000,000
    int total = out_size;      // NUM_SEG * DIM

    void* counts_ptr = nullptr;
    cudaGetSymbolAddress(&counts_ptr, g_counts);
    cudaMemsetAsync(out, 0, (size_t)total * sizeof(float), 0);
    cudaMemsetAsync(counts_ptr, 0, (size_t)NUM_SEG * sizeof(float), 0);

    int sb = (nrows + ROWS_PER_BLK - 1) / ROWS_PER_BLK;
    scatter_kernel<<<sb, TPB>>>(x, index, out, nrows);

    int total4 = total / 4;
    int db = 1184;   // 8 blocks/SM-ish; grid-stride covers the rest
    divide_kernel<<<db, TPB>>>((float4*)out, total4);
}